// round 14
// baseline (speedup 1.0000x reference)
#include <cuda_runtime.h>
#include <cuda_fp16.h>
#include <math.h>
#include <stdint.h>

#define B_ 8192
#define D_ 256
#define H_ 266
#define HP 272
#define T_ 20
#define NBLK 256
#define THREADS 256
#define EPS 1e-5f

typedef __half hf;

// ---------------- persistent state (no allocation allowed) ----------------
__device__ float g_x[B_ * D_];
__device__ hf g_xh[B_ * D_];
__device__ hf g_h1[B_ * HP];
__device__ hf g_h2[B_ * HP];
__device__ float g_as[3 * 288];
__device__ float g_aq[3 * 288];
__device__ float g_v[B_];
__device__ float g_yv[B_];
__device__ float g_s0[2];
__device__ unsigned g_pair[128];
__device__ unsigned g_cnt;
__device__ unsigned g_epoch;

// fp16 weights, K-padded so every row is 16B aligned
#define GW1 0                 // T*266 rows, stride 256
#define GW2 1361920           // T*266 rows, stride 272
#define GW3 2808960           // T*256 rows, stride 272
#define GVW1 4201600          // 266 rows, stride 256
#define GVW2 4269696          // 266 rows, stride 272
#define GWTOT 4342048
__device__ hf g_w[GWTOT];

// ---------------- smem layout (byte offsets) ----------------
// stage: A 64x72 hf (9216B) + B 144x72 hf (20736B) = 29952B; 3 stages
#define STGB 29952
#define OFF_SC 89856    // float[288]
#define OFF_SH 91008    // float[288]
#define OFF_SC2 92160   // half2[144]
#define OFF_SH2 92736   // half2[144]
#define OFF_RED 93312   // 4608B scratch
#define OFF_BC 97920    // float[8]
#define SMEM_BYTES 97952

// ---------------- low-level helpers ----------------
__device__ __forceinline__ uint32_t smem_u32(const void* p) {
    uint32_t a;
    asm("{ .reg .u64 t; cvta.to.shared.u64 t, %1; cvt.u32.u64 %0, t; }" : "=r"(a) : "l"(p));
    return a;
}
__device__ __forceinline__ void cpa16(uint32_t dst, const void* src, int sz) {
    asm volatile("cp.async.cg.shared.global [%0], [%1], 16, %2;" :: "r"(dst), "l"(src),
                 "r"(sz));
}
__device__ __forceinline__ uint32_t packhf(float a, float b) {
    __half2 t = __floats2half2_rn(a, b);
    return *(uint32_t*)&t;
}
#define MMAH(d, a, b0, b1)                                                    \
    asm volatile(                                                             \
        "mma.sync.aligned.m16n8k16.row.col.f32.f16.f16.f32 "                  \
        "{%0,%1,%2,%3},{%4,%5,%6,%7},{%8,%9},{%0,%1,%2,%3};"                  \
        : "+f"(d[0]), "+f"(d[1]), "+f"(d[2]), "+f"(d[3])                      \
        : "r"(a[0]), "r"(a[1]), "r"(a[2]), "r"(a[3]), "r"(b0), "r"(b1))
#define LDSM4(r, ad)                                                          \
    asm volatile("ldmatrix.sync.aligned.m8n8.x4.shared.b16 {%0,%1,%2,%3}, [%4];" \
                 : "=r"((r)[0]), "=r"((r)[1]), "=r"((r)[2]), "=r"((r)[3])     \
                 : "r"(ad))
#define LDSM2(r0, r1, ad)                                                     \
    asm volatile("ldmatrix.sync.aligned.m8n8.x2.shared.b16 {%0,%1}, [%2];"    \
                 : "=r"(r0), "=r"(r1) : "r"(ad))

// epoch-based global barrier (monotonic epoch; count self-resets)
__device__ __forceinline__ void gbar() {
    __syncthreads();
    if (threadIdx.x == 0) {
        unsigned e0 = *(volatile unsigned*)&g_epoch;
        __threadfence();
        unsigned old = atomicAdd(&g_cnt, 1u);
        if (old == NBLK - 1) {
            *(volatile unsigned*)&g_cnt = 0u;
            __threadfence();
            atomicAdd(&g_epoch, 1u);
        } else {
            while (*(volatile unsigned*)&g_epoch == e0) { __nanosleep(64); }
        }
        __threadfence();
    }
    __syncthreads();
}

// pair handshake: both n-halves of m-tile reached target count
__device__ __forceinline__ void pair_sync(int m, unsigned target) {
    __syncthreads();
    if (threadIdx.x == 0) {
        __threadfence();
        atomicAdd(&g_pair[m], 1u);
        while (*(volatile unsigned*)&g_pair[m] < target) { __nanosleep(32); }
        __threadfence();
    }
    __syncthreads();
}

// ---------------- finalize from atomic totals ----------------
__device__ __forceinline__ void finalize_direct(int slot, int zslot,
                                                const float* __restrict__ bng,
                                                const float* __restrict__ bnb,
                                                char* smc, int tid) {
    float* scS = (float*)(smc + OFF_SC);
    float* shS = (float*)(smc + OFF_SH);
    __half2* sc2 = (__half2*)(smc + OFF_SC2);
    __half2* sh2 = (__half2*)(smc + OFF_SH2);
    for (int n = tid; n < 288; n += THREADS) {
        if (n < H_) {
            float s = g_as[slot * 288 + n];
            float q = g_aq[slot * 288 + n];
            float mean = s * (1.f / B_);
            float var = q * (1.f / B_) - mean * mean;
            float inv = rsqrtf(var + EPS);
            float sc = bng[n] * inv;
            scS[n] = sc;
            shS[n] = bnb[n] - mean * sc;
        } else {
            scS[n] = 0.f;
            shS[n] = 0.f;
        }
        g_as[zslot * 288 + n] = 0.f;
        g_aq[zslot * 288 + n] = 0.f;
    }
    __syncthreads();
    if (tid < 144) {
        sc2[tid] = __floats2half2_rn(scS[2 * tid], scS[2 * tid + 1]);
        sh2[tid] = __floats2half2_rn(shS[2 * tid], shS[2 * tid + 1]);
    }
    __syncthreads();
}

// ---------------- cp.async issues (k=64 chunks, row stride 72 hf) ----------------
__device__ __forceinline__ void issueB(const hf* __restrict__ Wg, int klim, int nact,
                                       int half, int NH, char* smc, int tid, int ch) {
    hf* Bs = (hf*)(smc + (ch % 3) * STGB) + 4608;
    const int cnt = NH * 8;
#pragma unroll
    for (int l = 0; l < 5; l++) {
        int i = tid + l * THREADS;
        if (i < cnt) {
            int n = i >> 3, seg = i & 7, gk = ch * 64 + seg * 8;
            int ng = half * NH + n;
            int ok = (gk + 8 <= klim) && (ng < nact);
            const hf* src = Wg + (ok ? ((size_t)ng * klim + gk) : 0);
            cpa16(smem_u32(Bs + n * 72 + seg * 8), src, ok ? 16 : 0);
        }
    }
    asm volatile("cp.async.commit_group;" ::: "memory");
}
__device__ __forceinline__ void issueB2(const hf* Wg, int klim, int nact, int half,
                                        int NH, char* smc, int tid) {
    issueB(Wg, klim, nact, half, NH, smc, tid, 0);
    issueB(Wg, klim, nact, half, NH, smc, tid, 1);
}
__device__ __forceinline__ void issueA_body(const hf* __restrict__ Ag, int klim,
                                            char* smc, int m0, int tid, int ch) {
    hf* As = (hf*)(smc + (ch % 3) * STGB);
#pragma unroll
    for (int l = 0; l < 2; l++) {
        int i = tid + l * THREADS;
        int row = i >> 3, seg = i & 7, gk = ch * 64 + seg * 8;
        int ok = (gk + 8 <= klim);
        const hf* src = Ag + (size_t)(m0 + row) * klim + (ok ? gk : 0);
        cpa16(smem_u32(As + row * 72 + seg * 8), src, ok ? 16 : 0);
    }
}
__device__ __forceinline__ void issueA(const hf* Ag, int klim, char* smc, int m0,
                                       int tid, int ch) {
    issueA_body(Ag, klim, smc, m0, tid, ch);
    asm volatile("cp.async.commit_group;" ::: "memory");
}
__device__ __forceinline__ void issueAB(const hf* Ag, const hf* Wg, int klim, int nact,
                                        int half, int NH, char* smc, int m0, int tid,
                                        int ch) {
    issueA_body(Ag, klim, smc, m0, tid, ch);
    issueB(Wg, klim, nact, half, NH, smc, tid, ch);  // commits the group
}

// ---------------- GEMM mainloop (B chunks 0,1 pre-issued before the bar) ----------------
template <int NC, int LASTSL, bool AFFINE>
__device__ __forceinline__ void do_gemm(const hf* __restrict__ Ag,
                                        const hf* __restrict__ Wg, int klim, int nact,
                                        int NH, int slot, int zslot,
                                        const float* __restrict__ bng,
                                        const float* __restrict__ bnb, char* smc,
                                        int m0, int half, int tid, float acc[2][5][4]) {
    const int lane = tid & 31, w = tid >> 5, wm = w >> 2, wn = w & 3;
    int ntw, cbase;
    if (NH == 128) {
        ntw = 4;
        cbase = wn * 32;
    } else {
        ntw = (wn < 2) ? 5 : 4;
        cbase = (wn < 2) ? wn * 40 : 80 + (wn - 2) * 32;
    }
    const __half2* sc2 = (const __half2*)(smc + OFF_SC2);
    const __half2* sh2 = (const __half2*)(smc + OFF_SH2);

    if (AFFINE) finalize_direct(slot, zslot, bng, bnb, smc, tid);

    asm volatile("cp.async.wait_group 0;" ::: "memory");  // B0,B1 landed (pre-bar)
    issueA(Ag, klim, smc, m0, tid, 0);
    issueA(Ag, klim, smc, m0, tid, 1);

    const int jj = lane >> 3, rw = lane & 7;
    const int am_off = (jj & 1) * 8 + rw;
    const int ak_off = (jj >> 1) * 8;

    for (int ch = 0; ch < NC; ch++) {
        if (ch < NC - 1)
            asm volatile("cp.async.wait_group 1;" ::: "memory");
        else
            asm volatile("cp.async.wait_group 0;" ::: "memory");
        __syncthreads();
        if (ch + 2 < NC) issueAB(Ag, Wg, klim, nact, half, NH, smc, m0, tid, ch + 2);

        const hf* As = (const hf*)(smc + (ch % 3) * STGB);
        const hf* Bs = As + 4608;
        const int smax = (ch == NC - 1) ? LASTSL : 4;
#pragma unroll
        for (int sl = 0; sl < 4; sl++) {
            if (sl >= smax) break;
            uint32_t a[2][4];
#pragma unroll
            for (int mt = 0; mt < 2; mt++) {
                const int r = wm * 32 + mt * 16 + am_off;
                LDSM4(a[mt], smem_u32(As + r * 72 + sl * 16 + ak_off));
            }
            if (AFFINE) {
                const int idx = ch * 32 + sl * 8 + (lane & 3);
                const __half2 s0 = sc2[idx], h0 = sh2[idx];
                const __half2 s4 = sc2[idx + 4], h4 = sh2[idx + 4];
                const __half2 z = __floats2half2_rn(0.f, 0.f);
#pragma unroll
                for (int mt = 0; mt < 2; mt++) {
                    __half2 v;
                    v = *(__half2*)&a[mt][0];
                    v = __hmax2(__hfma2(v, s0, h0), z);
                    a[mt][0] = *(uint32_t*)&v;
                    v = *(__half2*)&a[mt][1];
                    v = __hmax2(__hfma2(v, s0, h0), z);
                    a[mt][1] = *(uint32_t*)&v;
                    v = *(__half2*)&a[mt][2];
                    v = __hmax2(__hfma2(v, s4, h4), z);
                    a[mt][2] = *(uint32_t*)&v;
                    v = *(__half2*)&a[mt][3];
                    v = __hmax2(__hfma2(v, s4, h4), z);
                    a[mt][3] = *(uint32_t*)&v;
                }
            }
            uint32_t b[5][2];
#pragma unroll
            for (int p = 0; p < 2; p++) {
                const int ntp = p * 2 + (jj >> 1);
                const int kb = (jj & 1) * 8;
                const int rowb = cbase + ntp * 8 + rw;
                uint32_t r4[4];
                LDSM4(r4, smem_u32(Bs + rowb * 72 + sl * 16 + kb));
                b[2 * p][0] = r4[0];
                b[2 * p][1] = r4[1];
                b[2 * p + 1][0] = r4[2];
                b[2 * p + 1][1] = r4[3];
            }
            if (ntw == 5) {
                const int kb = (jj & 1) * 8;
                const int rowb = cbase + 32 + rw;
                LDSM2(b[4][0], b[4][1], smem_u32(Bs + rowb * 72 + sl * 16 + kb));
            }
#pragma unroll
            for (int nt = 0; nt < 5; nt++) {
                if (nt < ntw) {
                    MMAH(acc[0][nt], a[0], b[nt][0], b[nt][1]);
                    MMAH(acc[1][nt], a[1], b[nt][0], b[nt][1]);
                }
            }
        }
    }
    __syncthreads();
}

// ---------------- epilogue: bias, hf Y store, column stats -> atomic slot ----------------
// stats layers always have NH=144 (N=266 split)
__device__ __forceinline__ void epi_stats(float acc[2][5][4], const float* __restrict__ bias,
                                          hf* __restrict__ Yg, int slot, char* smc,
                                          int m0, int half, int tid) {
    const int lane = tid & 31, w = tid >> 5, wm = w >> 2, wn = w & 3;
    const int ntw = (wn < 2) ? 5 : 4;
    const int cbase = (wn < 2) ? wn * 40 : 80 + (wn - 2) * 32;
    float* ps = (float*)(smc + OFF_RED);
    float* pq = ps + 320;
#pragma unroll
    for (int nt = 0; nt < 5; nt++) {
        if (nt >= ntw) continue;
        const int cl = cbase + nt * 8 + 2 * (lane & 3);
        const int ng = half * 144 + cl;
        float b0 = 0.f, b1 = 0.f;
        if (ng < H_) { b0 = bias[ng]; b1 = bias[ng + 1]; }
        float s0 = 0.f, s1 = 0.f, q0 = 0.f, q1 = 0.f;
#pragma unroll
        for (int mt = 0; mt < 2; mt++) {
            const int rbase = m0 + wm * 32 + mt * 16 + (lane >> 2);
#pragma unroll
            for (int rs = 0; rs < 2; rs++) {
                float y0 = acc[mt][nt][rs * 2 + 0] + b0;
                float y1 = acc[mt][nt][rs * 2 + 1] + b1;
                const int row = rbase + rs * 8;
                if (ng < H_)
                    *(uint32_t*)(Yg + (size_t)row * HP + ng) = packhf(y0, y1);
                else if (ng < HP)
                    *(uint32_t*)(Yg + (size_t)row * HP + ng) = 0u;
                s0 += y0; s1 += y1;
                q0 += y0 * y0; q1 += y1 * y1;
            }
        }
#pragma unroll
        for (int m = 4; m <= 16; m <<= 1) {
            s0 += __shfl_xor_sync(~0u, s0, m);
            s1 += __shfl_xor_sync(~0u, s1, m);
            q0 += __shfl_xor_sync(~0u, q0, m);
            q1 += __shfl_xor_sync(~0u, q1, m);
        }
        if (lane < 4) {
            ps[w * 40 + nt * 8 + 2 * lane] = s0;
            ps[w * 40 + nt * 8 + 2 * lane + 1] = s1;
            pq[w * 40 + nt * 8 + 2 * lane] = q0;
            pq[w * 40 + nt * 8 + 2 * lane + 1] = q1;
        }
    }
    __syncthreads();
    if (tid < 144) {
        const int nl = tid;
        const int wn2 = (nl < 80) ? (nl / 40) : (2 + (nl - 80) / 32);
        const int loc = (nl < 80) ? (nl % 40) : ((nl - 80) % 32);
        float s = ps[wn2 * 40 + loc] + ps[(4 + wn2) * 40 + loc];
        float q = pq[wn2 * 40 + loc] + pq[(4 + wn2) * 40 + loc];
        const int ng = half * 144 + nl;
        if (ng < H_) {
            atomicAdd(&g_as[slot * 288 + ng], s);
            atomicAdd(&g_aq[slot * 288 + ng], q);
        }
    }
    __syncthreads();
}

// ---------------- L3 epilogue fused with SDE update (NH=128) ----------------
__device__ __forceinline__ void epi_update(float acc[2][5][4], const float* __restrict__ b3,
                                           const float* __restrict__ xi_t,
                                           const float* __restrict__ xsrc,
                                           float* __restrict__ xdst,
                                           hf* __restrict__ xh, float ht, char* smc,
                                           int m0, int half, int tid) {
    const int lane = tid & 31, w = tid >> 5, wm = w >> 2, wn = w & 3;
    const float sq = sqrtf(ht);
    float fa[2][2] = {}, da[2][2] = {};
#pragma unroll
    for (int nt = 0; nt < 4; nt++) {
        const int ng = half * 128 + wn * 32 + nt * 8 + 2 * (lane & 3);
        const float b0 = b3[ng], b1 = b3[ng + 1];
#pragma unroll
        for (int mt = 0; mt < 2; mt++) {
#pragma unroll
            for (int rs = 0; rs < 2; rs++) {
                const int row = m0 + wm * 32 + mt * 16 + (lane >> 2) + rs * 8;
                float gg0 = acc[mt][nt][rs * 2 + 0] + b0;
                float gg1 = acc[mt][nt][rs * 2 + 1] + b1;
                float2 xi2 = *(const float2*)(xi_t + (size_t)row * 256 + ng);
                float2 xs2 = *(const float2*)(xsrc + (size_t)row * 256 + ng);
                float n0 = sq * xi2.x, n1 = sq * xi2.y;
                fa[mt][rs] += gg0 * gg0 + gg1 * gg1;
                da[mt][rs] += gg0 * n0 + gg1 * n1;
                float xn0 = xs2.x - gg0 * ht + n0;
                float xn1 = xs2.y - gg1 * ht + n1;
                *(float2*)(xdst + (size_t)row * 256 + ng) = make_float2(xn0, xn1);
                if (xh)
                    *(uint32_t*)(xh + (size_t)row * 256 + ng) = packhf(xn0, xn1);
            }
        }
    }
#pragma unroll
    for (int m = 1; m <= 2; m <<= 1) {
#pragma unroll
        for (int mt = 0; mt < 2; mt++)
#pragma unroll
            for (int rs = 0; rs < 2; rs++) {
                fa[mt][rs] += __shfl_xor_sync(~0u, fa[mt][rs], m);
                da[mt][rs] += __shfl_xor_sync(~0u, da[mt][rs], m);
            }
    }
    float* rf = (float*)(smc + OFF_RED);
    float* rd = rf + 256;
    if ((lane & 3) == 0) {
#pragma unroll
        for (int mt = 0; mt < 2; mt++)
#pragma unroll
            for (int rs = 0; rs < 2; rs++) {
                int rl = wm * 32 + mt * 16 + (lane >> 2) + rs * 8;
                rf[wn * 64 + rl] = fa[mt][rs];
                rd[wn * 64 + rl] = da[mt][rs];
            }
    }
    __syncthreads();
    if (tid < 64) {
        float F = 0.f, Dt = 0.f;
#pragma unroll
        for (int j = 0; j < 4; j++) {
            F += rf[j * 64 + tid];
            Dt += rd[j * 64 + tid];
        }
        atomicAdd(&g_v[m0 + tid], -F * ht + Dt);
    }
    __syncthreads();
}

// ---------------- v0 tail ----------------
__device__ __forceinline__ void v3_part(const hf* __restrict__ h2,
                                        const float* __restrict__ vW3,
                                        const float* __restrict__ vb3, char* smc,
                                        int m0, int half, int tid) {
    const int lane = tid & 31, w = tid >> 5;
    const float* scS = (const float*)(smc + OFF_SC);
    const float* shS = (const float*)(smc + OFF_SH);
    const int k0 = half * 144, k1 = half ? H_ : 144;
    for (int i = 0; i < 8; i++) {
        int row = m0 + w * 8 + i;
        size_t base = (size_t)row * HP;
        float s = 0.f;
        for (int k = k0 + lane; k < k1; k += 32) {
            float hv = __half2float(h2[base + k]);
            float a2 = fmaxf(fmaf(hv, scS[k], shS[k]), 0.f);
            s = fmaf(a2, vW3[k], s);
        }
#pragma unroll
        for (int m = 16; m > 0; m >>= 1) s += __shfl_xor_sync(~0u, s, m);
        if (lane == 0) atomicAdd(&g_yv[row], s + (half ? 0.f : vb3[0]));
    }
    __syncthreads();
}

// ---------------- the persistent mega-kernel ----------------
__global__ void __launch_bounds__(THREADS, 2) mega(
    const float* __restrict__ x, const float* __restrict__ xi,
    const float* __restrict__ tg, const float* __restrict__ W1,
    const float* __restrict__ b1, const float* __restrict__ g1,
    const float* __restrict__ be1, const float* __restrict__ W2,
    const float* __restrict__ b2, const float* __restrict__ g2,
    const float* __restrict__ be2, const float* __restrict__ W3,
    const float* __restrict__ b3, const float* __restrict__ vW1,
    const float* __restrict__ vb1, const float* __restrict__ vg1,
    const float* __restrict__ vbe1, const float* __restrict__ vW2,
    const float* __restrict__ vb2, const float* __restrict__ vg2,
    const float* __restrict__ vbe2, const float* __restrict__ vW3,
    const float* __restrict__ vb3, const float* __restrict__ vg3,
    const float* __restrict__ vbe3, float* __restrict__ out) {
    extern __shared__ char smc[];
    const int bid = blockIdx.x, tid = threadIdx.x;
    const int mI = bid >> 1, half = bid & 1;
    const int m0 = mI * 64;

    // ---- phase 0: convert weights + x; zero accumulators (once) ----
    {
        const int gt = bid * THREADS + tid, gs = NBLK * THREADS;
        for (int i = gt; i < T_ * H_ * D_; i += gs)
            g_w[GW1 + i] = __float2half(W1[i]);
        for (int i = gt; i < T_ * H_ * HP; i += gs) {
            int r = i / HP, k = i - r * HP;
            g_w[GW2 + i] = (k < H_) ? __float2half(W2[r * H_ + k]) : __float2half(0.f);
        }
        for (int i = gt; i < T_ * D_ * HP; i += gs) {
            int r = i / HP, k = i - r * HP;
            g_w[GW3 + i] = (k < H_) ? __float2half(W3[r * H_ + k]) : __float2half(0.f);
        }
        for (int i = gt; i < H_ * D_; i += gs)
            g_w[GVW1 + i] = __float2half(vW1[i]);
        for (int i = gt; i < H_ * HP; i += gs) {
            int r = i / HP, k = i - r * HP;
            g_w[GVW2 + i] = (k < H_) ? __float2half(vW2[r * H_ + k]) : __float2half(0.f);
        }
        for (int i = gt; i < B_ * D_; i += gs) g_xh[i] = __float2half(x[i]);
        for (int i = gt; i < 3 * 288; i += gs) { g_as[i] = 0.f; g_aq[i] = 0.f; }
        for (int i = gt; i < B_; i += gs) g_yv[i] = 0.f;
        for (int i = gt; i < 128; i += gs) g_pair[i] = 0u;
        if (gt < 2) g_s0[gt] = 0.f;
    }
    gbar();

    int bn = 0;

    // ---- v0 network ----
    issueB2(g_w + GVW1, 256, 266, half, 144, smc, tid);
    {
        float acc[2][5][4] = {};
        do_gemm<4, 4, false>(g_xh, g_w + GVW1, 256, 266, 144, 0, 0, nullptr, nullptr,
                             smc, m0, half, tid, acc);
        epi_stats(acc, vb1, g_h1, bn % 3, smc, m0, half, tid);
    }
    issueB2(g_w + GVW2, 272, 266, half, 144, smc, tid);
    gbar();
    {
        float acc[2][5][4] = {};
        do_gemm<5, 1, true>(g_h1, g_w + GVW2, 272, 266, 144, bn % 3, (bn + 2) % 3, vg1,
                            vbe1, smc, m0, half, tid, acc);
        bn++;
        epi_stats(acc, vb2, g_h2, bn % 3, smc, m0, half, tid);
    }
    gbar();
    finalize_direct(bn % 3, (bn + 2) % 3, vg2, vbe2, smc, tid);
    bn++;
    v3_part(g_h2, vW3, vb3, smc, m0, half, tid);
    gbar();
    if (half == 0) {
        // scalar stats over own 64 rows
        float s = 0.f, q = 0.f;
        if (tid < 64) {
            float t = g_yv[m0 + tid];
            s = t;
            q = t * t;
        }
#pragma unroll
        for (int m = 16; m > 0; m >>= 1) {
            s += __shfl_xor_sync(~0u, s, m);
            q += __shfl_xor_sync(~0u, q, m);
        }
        __shared__ float red2[4];
        if ((tid & 31) == 0 && tid < 64) {
            ((float*)(smc + OFF_BC))[4 + (tid >> 5)] = s;
            ((float*)(smc + OFF_BC))[6 + (tid >> 5)] = q;
        }
        __syncthreads();
        if (tid == 0) {
            float* bc = (float*)(smc + OFF_BC);
            atomicAdd(&g_s0[0], bc[4] + bc[5]);
            atomicAdd(&g_s0[1], bc[6] + bc[7]);
        }
        (void)red2;
    }
    gbar();
    if (half == 0) {
        float* bc = (float*)(smc + OFF_BC);
        if (tid == 0) {
            float m = g_s0[0] * (1.f / B_);
            float var = g_s0[1] * (1.f / B_) - m * m;
            float inv = rsqrtf(var + EPS);
            float sc = vg3[0] * inv;
            bc[0] = sc;
            bc[1] = vbe3[0] - m * sc;
        }
        __syncthreads();
        if (tid < 64)
            g_v[m0 + tid] = fmaxf(fmaf(g_yv[m0 + tid], bc[0], bc[1]), 0.f);
    }
    gbar();  // v0 in g_v visible to all before scan's atomic adds

    issueB2(g_w + GW1, 256, 266, half, 144, smc, tid);

    // ---- time-stepping scan ----
    for (int t = 0; t < T_; t++) {
        const float* xsrc = (t == 0) ? x : g_x;
        const hf* W1t = g_w + GW1 + (size_t)t * H_ * D_;
        const hf* W2t = g_w + GW2 + (size_t)t * H_ * HP;
        const hf* W3t = g_w + GW3 + (size_t)t * D_ * HP;
        const float* b1t = b1 + (size_t)t * H_;
        const float* g1t = g1 + (size_t)t * H_;
        const float* be1t = be1 + (size_t)t * H_;
        const float* b2t = b2 + (size_t)t * H_;
        const float* g2t = g2 + (size_t)t * H_;
        const float* be2t = be2 + (size_t)t * H_;
        const float* b3t = b3 + (size_t)t * D_;
        const float* xit = xi + (size_t)t * B_ * D_;

        {
            float acc[2][5][4] = {};
            do_gemm<4, 4, false>(g_xh, W1t, 256, 266, 144, 0, 0, nullptr, nullptr, smc,
                                 m0, half, tid, acc);
            epi_stats(acc, b1t, g_h1, bn % 3, smc, m0, half, tid);
        }
        issueB2(W2t, 272, 266, half, 144, smc, tid);
        gbar();
        {
            float acc[2][5][4] = {};
            do_gemm<5, 1, true>(g_h1, W2t, 272, 266, 144, bn % 3, (bn + 2) % 3, g1t,
                                be1t, smc, m0, half, tid, acc);
            bn++;
            epi_stats(acc, b2t, g_h2, bn % 3, smc, m0, half, tid);
        }
        issueB2(W3t, 272, 256, half, 128, smc, tid);
        gbar();
        {
            float acc[2][5][4] = {};
            do_gemm<5, 1, true>(g_h2, W3t, 272, 256, 128, bn % 3, (bn + 2) % 3, g2t,
                                be2t, smc, m0, half, tid, acc);
            bn++;
            float ht = tg[t + 1] - tg[t];
            float* xdst = (t == T_ - 1) ? (out + B_) : g_x;
            hf* xh = (t == T_ - 1) ? nullptr : g_xh;
            epi_update(acc, b3t, xit, xsrc, xdst, xh, ht, smc, m0, half, tid);
        }
        if (t + 1 < T_) {
            issueB2(g_w + GW1 + (size_t)(t + 1) * H_ * D_, 256, 266, half, 144, smc, tid);
            pair_sync(mI, 2u * (unsigned)(t + 1));
        }
    }

    // ---- output v ----
    gbar();
    if (half == 0 && tid < 64) out[m0 + tid] = g_v[m0 + tid];
}

// ---------------- host ----------------
extern "C" void kernel_launch(void* const* d_in, const int* in_sizes, int n_in,
                              void* d_out, int out_size) {
    const float* x    = (const float*)d_in[0];
    const float* xi   = (const float*)d_in[1];
    const float* tg   = (const float*)d_in[2];
    const float* W1   = (const float*)d_in[3];
    const float* b1   = (const float*)d_in[4];
    const float* g1   = (const float*)d_in[5];
    const float* be1  = (const float*)d_in[6];
    const float* W2   = (const float*)d_in[7];
    const float* b2   = (const float*)d_in[8];
    const float* g2   = (const float*)d_in[9];
    const float* be2  = (const float*)d_in[10];
    const float* W3   = (const float*)d_in[11];
    const float* b3   = (const float*)d_in[12];
    const float* vW1  = (const float*)d_in[13];
    const float* vb1  = (const float*)d_in[14];
    const float* vg1  = (const float*)d_in[15];
    const float* vbe1 = (const float*)d_in[16];
    const float* vW2  = (const float*)d_in[17];
    const float* vb2  = (const float*)d_in[18];
    const float* vg2  = (const float*)d_in[19];
    const float* vbe2 = (const float*)d_in[20];
    const float* vW3  = (const float*)d_in[21];
    const float* vb3  = (const float*)d_in[22];
    const float* vg3  = (const float*)d_in[23];
    const float* vbe3 = (const float*)d_in[24];

    cudaFuncSetAttribute(mega, cudaFuncAttributeMaxDynamicSharedMemorySize, SMEM_BYTES);
    mega<<<NBLK, THREADS, SMEM_BYTES>>>(x, xi, tg, W1, b1, g1, be1, W2, b2, g2, be2,
                                        W3, b3, vW1, vb1, vg1, vbe1, vW2, vb2, vg2,
                                        vbe2, vW3, vb3, vg3, vbe3, (float*)d_out);
}